// round 4
// baseline (speedup 1.0000x reference)
#include <cuda_runtime.h>
#include <math.h>

#define BATCH 4
#define SEQ   1024
#define EMBED 2048
#define NHEAD 16
#define HDIM  128
#define MROWS (BATCH*SEQ)     // 4096
#define BH    (BATCH*NHEAD)   // 64

// Scratch (device globals; no allocation allowed in kernel_launch)
__device__ float g_q[(size_t)MROWS*EMBED];     // [B,H,S,D] after proj
__device__ float g_k[(size_t)MROWS*EMBED];     // [B,H,S,D]
__device__ float g_v[(size_t)MROWS*EMBED];     // [B,H,S,D]
__device__ float g_s[(size_t)BH*SEQ*SEQ];      // scores / probs
__device__ float g_ctx[(size_t)MROWS*EMBED];   // [B,S,E]

#define BM 128
#define BN 128
#define BK 16
#define TM 8
#define TN 8

// C = alpha * A @ B^T ; A[M,K] lda, B[N,K] ldb (both K-contiguous).
// mode bit0: causal block-skip (bx>by).  mode bit1: permute output
// [m=(b,s), n=(h,d)] -> [b,h,s,d].  z-batched via strides.
__global__ void __launch_bounds__(256) gemm_nt(
    const float* __restrict__ A, const float* __restrict__ B, float* __restrict__ C,
    int M, int N, int K, int lda, int ldb, int ldc,
    long sA, long sB, long sC, float alpha, int mode)
{
    int bx = blockIdx.x, by = blockIdx.y, bz = blockIdx.z;
    if ((mode & 1) && bx > by) return;
    A += (long)bz * sA; B += (long)bz * sB; C += (long)bz * sC;

    __shared__ float As[BK][BM];
    __shared__ float Bs[BK][BN];

    int tid = threadIdx.x;
    int tx = tid & 15, ty = tid >> 4;

    const float* Ab = A + (long)by * BM * lda;
    const float* Bb = B + (long)bx * BN * ldb;

    float acc[TM][TN];
    #pragma unroll
    for (int i = 0; i < TM; i++)
        #pragma unroll
        for (int j = 0; j < TN; j++) acc[i][j] = 0.f;

    for (int k0 = 0; k0 < K; k0 += BK) {
        #pragma unroll
        for (int j = 0; j < 2; j++) {
            int i = tid * 2 + j;            // 0..511
            int row = i >> 2;
            int c4  = i & 3;
            float4 v = *(const float4*)(Ab + (long)row * lda + k0 + c4 * 4);
            As[c4*4+0][row] = v.x; As[c4*4+1][row] = v.y;
            As[c4*4+2][row] = v.z; As[c4*4+3][row] = v.w;
        }
        #pragma unroll
        for (int j = 0; j < 2; j++) {
            int i = tid * 2 + j;
            int row = i >> 2;
            int c4  = i & 3;
            float4 v = *(const float4*)(Bb + (long)row * ldb + k0 + c4 * 4);
            Bs[c4*4+0][row] = v.x; Bs[c4*4+1][row] = v.y;
            Bs[c4*4+2][row] = v.z; Bs[c4*4+3][row] = v.w;
        }
        __syncthreads();
        #pragma unroll
        for (int kk = 0; kk < BK; kk++) {
            float ra[TM], rb[TN];
            #pragma unroll
            for (int i = 0; i < TM; i++) ra[i] = As[kk][ty*TM + i];
            #pragma unroll
            for (int j = 0; j < TN; j++) rb[j] = Bs[kk][tx*TN + j];
            #pragma unroll
            for (int i = 0; i < TM; i++)
                #pragma unroll
                for (int j = 0; j < TN; j++)
                    acc[i][j] += ra[i] * rb[j];
        }
        __syncthreads();
    }

    if (mode & 2) {
        #pragma unroll
        for (int i = 0; i < TM; i++) {
            int row = by*BM + ty*TM + i;
            int b = row / SEQ, s = row % SEQ;
            #pragma unroll
            for (int j = 0; j < TN; j++) {
                int col = bx*BN + tx*TN + j;
                int h = col / HDIM, d = col % HDIM;
                long dst = ((long)b * NHEAD + h) * (long)(SEQ * HDIM)
                         + (long)s * HDIM + d;
                C[dst] = alpha * acc[i][j];
            }
        }
    } else {
        #pragma unroll
        for (int i = 0; i < TM; i++) {
            long row = by*BM + ty*TM + i;
            #pragma unroll
            for (int j = 0; j < TN; j++) {
                int col = bx*BN + tx*TN + j;
                C[row * ldc + col] = alpha * acc[i][j];
            }
        }
    }
}

// C[q,d] += A[q,k] * B[k,d]  (NN).  A = probs (lda=SEQ), B = V[bh] (ldb=HDIM).
// Output hard-wired to g_ctx in [B,S,E] layout. causal: k-loop stops at diag.
__global__ void __launch_bounds__(256) gemm_nn_av(
    const float* __restrict__ A, const float* __restrict__ B,
    int K, int lda, int ldb, long sA, long sB)
{
    int bx = blockIdx.x, by = blockIdx.y, bz = blockIdx.z;
    A += (long)bz * sA; B += (long)bz * sB;
    int b = bz / NHEAD, h = bz % NHEAD;

    __shared__ float As[BK][BM];
    __shared__ float Bs[BK][BN];

    int tid = threadIdx.x;
    int tx = tid & 15, ty = tid >> 4;

    const float* Ab = A + (long)by * BM * lda;

    float acc[TM][TN];
    #pragma unroll
    for (int i = 0; i < TM; i++)
        #pragma unroll
        for (int j = 0; j < TN; j++) acc[i][j] = 0.f;

    int kEnd = min(K, (by + 1) * BM);   // probs are 0 beyond the diagonal
    for (int k0 = 0; k0 < kEnd; k0 += BK) {
        #pragma unroll
        for (int j = 0; j < 2; j++) {
            int i = tid * 2 + j;
            int row = i >> 2;
            int c4  = i & 3;
            float4 v = *(const float4*)(Ab + (long)row * lda + k0 + c4 * 4);
            As[c4*4+0][row] = v.x; As[c4*4+1][row] = v.y;
            As[c4*4+2][row] = v.z; As[c4*4+3][row] = v.w;
        }
        #pragma unroll
        for (int j = 0; j < 2; j++) {
            int i = tid * 2 + j;            // 0..511
            int r  = i >> 5;                // 0..15
            int c4 = i & 31;                // 0..31
            float4 v = *(const float4*)(B + (long)(k0 + r) * ldb + c4 * 4);
            *(float4*)&Bs[r][c4 * 4] = v;
        }
        __syncthreads();
        #pragma unroll
        for (int kk = 0; kk < BK; kk++) {
            float ra[TM], rb[TN];
            #pragma unroll
            for (int i = 0; i < TM; i++) ra[i] = As[kk][ty*TM + i];
            #pragma unroll
            for (int j = 0; j < TN; j++) rb[j] = Bs[kk][tx*TN + j];
            #pragma unroll
            for (int i = 0; i < TM; i++)
                #pragma unroll
                for (int j = 0; j < TN; j++)
                    acc[i][j] += ra[i] * rb[j];
        }
        __syncthreads();
    }

    #pragma unroll
    for (int i = 0; i < TM; i++) {
        int q = by*BM + ty*TM + i;
        #pragma unroll
        for (int j = 0; j < TN; j++) {
            int d = bx*BN + tx*TN + j;
            g_ctx[((long)b * SEQ + q) * EMBED + h * HDIM + d] = acc[i][j];
        }
    }
}

// In-place rotate-half RoPE on [BH, S, D] tensor.
__global__ void rope_kernel(float* __restrict__ x,
                            const float* __restrict__ cosT,
                            const float* __restrict__ sinT)
{
    long i = (long)blockIdx.x * blockDim.x + threadIdx.x;
    long total = (long)BH * SEQ * (HDIM / 2);
    if (i >= total) return;
    int d = (int)(i % (HDIM / 2));
    long rs = i / (HDIM / 2);           // bh*SEQ + s
    int s = (int)(rs % SEQ);
    float* base = x + rs * HDIM;
    float x1 = base[d], x2 = base[d + HDIM/2];
    float c1 = cosT[s*HDIM + d],          s1 = sinT[s*HDIM + d];
    float c2 = cosT[s*HDIM + d + HDIM/2], s2 = sinT[s*HDIM + d + HDIM/2];
    base[d]          = x1 * c1 - x2 * s1;
    base[d + HDIM/2] = x2 * c2 + x1 * s2;
}

// Causal softmax over rows of g_s. One block per (bh,q) row.
__global__ void __launch_bounds__(256) softmax_kernel()
{
    long row = blockIdx.x;              // 0 .. BH*SEQ-1
    int q = (int)(row % SEQ);
    float* p = g_s + row * (long)SEQ;
    __shared__ float red[256];
    int tid = threadIdx.x;

    float m = -1e30f;
    for (int i = tid; i <= q; i += 256) m = fmaxf(m, p[i]);
    red[tid] = m; __syncthreads();
    for (int s = 128; s > 0; s >>= 1) {
        if (tid < s) red[tid] = fmaxf(red[tid], red[tid + s]);
        __syncthreads();
    }
    float mx = red[0]; __syncthreads();

    float sum = 0.f;
    for (int i = tid; i <= q; i += 256) {
        float e = __expf(p[i] - mx);
        p[i] = e;
        sum += e;
    }
    red[tid] = sum; __syncthreads();
    for (int s = 128; s > 0; s >>= 1) {
        if (tid < s) red[tid] += red[tid + s];
        __syncthreads();
    }
    float inv = 1.f / red[0];

    for (int i = tid; i <= q; i += 256) p[i] *= inv;
    for (int i = q + 1 + tid; i < SEQ; i += 256) p[i] = 0.f;
}

extern "C" void kernel_launch(void* const* d_in, const int* in_sizes, int n_in,
                              void* d_out, int out_size)
{
    const float* inQ  = (const float*)d_in[0];
    const float* inK  = (const float*)d_in[1];
    const float* inV  = (const float*)d_in[2];
    // d_in[3] = mask (causal, hard-coded)
    const float* cosT = (const float*)d_in[4];
    const float* sinT = (const float*)d_in[5];
    const float* Wq   = (const float*)d_in[6];
    const float* Wk   = (const float*)d_in[7];
    const float* Wv   = (const float*)d_in[8];
    const float* Wo   = (const float*)d_in[9];
    float* out = (float*)d_out;

    float *gq, *gk, *gv, *gs, *gctx;
    cudaGetSymbolAddress((void**)&gq,   g_q);
    cudaGetSymbolAddress((void**)&gk,   g_k);
    cudaGetSymbolAddress((void**)&gv,   g_v);
    cudaGetSymbolAddress((void**)&gs,   g_s);
    cudaGetSymbolAddress((void**)&gctx, g_ctx);

    dim3 projGrid(EMBED / BN, MROWS / BM, 1);   // 16 x 32
    // Q/K/V projections, output permuted to [B,H,S,D]
    gemm_nt<<<projGrid, 256>>>(inQ, Wq, gq, MROWS, EMBED, EMBED,
                               EMBED, EMBED, EMBED, 0, 0, 0, 1.0f, 2);
    gemm_nt<<<projGrid, 256>>>(inK, Wk, gk, MROWS, EMBED, EMBED,
                               EMBED, EMBED, EMBED, 0, 0, 0, 1.0f, 2);
    gemm_nt<<<projGrid, 256>>>(inV, Wv, gv, MROWS, EMBED, EMBED,
                               EMBED, EMBED, EMBED, 0, 0, 0, 1.0f, 2);

    // RoPE on Q and K
    long ropeN = (long)BH * SEQ * (HDIM / 2);
    int ropeBlocks = (int)((ropeN + 255) / 256);
    rope_kernel<<<ropeBlocks, 256>>>(gq, cosT, sinT);
    rope_kernel<<<ropeBlocks, 256>>>(gk, cosT, sinT);

    // scores = Q @ K^T / sqrt(D), causal block-skip
    float scale = 1.0f / sqrtf((float)HDIM);
    dim3 scGrid(SEQ / BN, SEQ / BM, BH);        // 8 x 8 x 64
    gemm_nt<<<scGrid, 256>>>(gq, gk, gs, SEQ, SEQ, HDIM,
                             HDIM, HDIM, SEQ,
                             (long)SEQ * HDIM, (long)SEQ * HDIM,
                             (long)SEQ * SEQ, scale, 1);

    // causal softmax
    softmax_kernel<<<BH * SEQ, 256>>>();

    // context = P @ V  (into [B,S,E])
    dim3 avGrid(HDIM / BN, SEQ / BM, BH);       // 1 x 8 x 64
    gemm_nn_av<<<avGrid, 256>>>(gs, gv, SEQ, SEQ, HDIM,
                                (long)SEQ * SEQ, (long)SEQ * HDIM);

    // out = ctx @ Wo^T
    gemm_nt<<<projGrid, 256>>>(gctx, Wo, out, MROWS, EMBED, EMBED,
                               EMBED, EMBED, EMBED, 0, 0, 0, 1.0f, 0);
}

// round 9
// speedup vs baseline: 2.5217x; 2.5217x over previous
#include <cuda_runtime.h>
#include <cstdint>
#include <math.h>

#define BATCH 4
#define SEQ   1024
#define EMBED 2048
#define NHEAD 16
#define HDIM  128
#define MROWS (BATCH*SEQ)     // 4096
#define BH    (BATCH*NHEAD)   // 64

#define BM 128
#define BN 128
#define BK 32

// Dynamic smem: max( double-buffer 2*(16KB+16KB)=64KB, epilogue 128*132*4=67584 )
#define SMEM_BYTES 67584

// Scratch
__device__ float g_q[(size_t)MROWS*EMBED];     // [B,S,E] = [b,s,h,d]
__device__ float g_k[(size_t)MROWS*EMBED];     // [B,S,E]
__device__ float g_v[(size_t)BH*HDIM*SEQ];     // [b,h,d,s]  (transposed V)
__device__ float g_s[(size_t)BH*SEQ*SEQ];      // scores / probs
__device__ float g_ctx[(size_t)MROWS*EMBED];   // [B,S,E]

__device__ __forceinline__ uint32_t f2tf32(float f) {
    uint32_t u;
    asm("cvt.rna.tf32.f32 %0, %1;" : "=r"(u) : "f"(f));
    return u;
}

__device__ __forceinline__ void mma_tf32(float& d0, float& d1, float& d2, float& d3,
                                         uint32_t a0, uint32_t a1, uint32_t a2, uint32_t a3,
                                         uint32_t b0, uint32_t b1) {
    asm volatile(
        "mma.sync.aligned.m16n8k8.row.col.f32.tf32.tf32.f32 "
        "{%0,%1,%2,%3}, {%4,%5,%6,%7}, {%8,%9}, {%0,%1,%2,%3};"
        : "+f"(d0), "+f"(d1), "+f"(d2), "+f"(d3)
        : "r"(a0), "r"(a1), "r"(a2), "r"(a3), "r"(b0), "r"(b1));
}

// ---------------- Generic tf32 mma.sync GEMM: C = alpha * A @ B^T ----------------
// A[M,K] lda, B[N,K] ldb (both K-contiguous).  z-batched via (z1,z2) strides.
// mode bit0: causal block-skip (bx>by)
// mode bit1: k-truncate at diagonal (AV)
// mode bit2: V-permute epilogue ([m=(b,s), n=(h=bx,d)] -> [b,h,d,s]); else row-major C.
__global__ void __launch_bounds__(256, 2) gemm_tc(
    const float* __restrict__ A, const float* __restrict__ B, float* __restrict__ C,
    int lda, int ldb, int ldc,
    long sA1, long sA2, long sB1, long sB2, long sC1, long sC2,
    int zdiv, int nChunks, float alpha, int mode)
{
    int bx = blockIdx.x, by = blockIdx.y, bz = blockIdx.z;
    if ((mode & 1) && bx > by) return;
    int z1 = bz / zdiv, z2 = bz % zdiv;
    A += z1 * sA1 + z2 * sA2;
    B += z1 * sB1 + z2 * sB2;
    C += z1 * sC1 + z2 * sC2;
    const float* Ab = A + (long)by * BM * lda;
    const float* Bb = B + (long)bx * BN * ldb;

    extern __shared__ __align__(16) uint32_t sm[];

    int tid  = threadIdx.x;
    int lane = tid & 31, warp = tid >> 5;
    int g = lane >> 2, tig = lane & 3;
    int wm = warp & 1, wn = warp >> 1;          // 2 x 4 warp grid (64x32 tiles)

    float acc[4][4][4];
    #pragma unroll
    for (int mt = 0; mt < 4; mt++)
        #pragma unroll
        for (int nt = 0; nt < 4; nt++)
            #pragma unroll
            for (int e = 0; e < 4; e++) acc[mt][nt][e] = 0.f;

    int nCh = nChunks;
    if (mode & 2) nCh = min(nCh, (by + 1) * (BM / BK));

    float4 ra[4], rb[4];

    // global -> regs (coalesced: k fast within warp)
    auto g_load = [&](int c) {
        #pragma unroll
        for (int p = 0; p < 4; p++) {
            int f = tid + p * 256;
            int k4 = f & 7, row = f >> 3;
            ra[p] = *(const float4*)(Ab + (long)row * lda + c * BK + k4 * 4);
            rb[p] = *(const float4*)(Bb + (long)row * ldb + c * BK + k4 * 4);
        }
    };
    // regs -> smem (tf32 convert, swizzled cells: u = k4*128 + (row^k4))
    auto s_store = [&](int stage) {
        uint32_t* bA = sm + stage * 8192;
        uint32_t* bB = bA + 4096;
        #pragma unroll
        for (int p = 0; p < 4; p++) {
            int f = tid + p * 256;
            int k4 = f & 7, row = f >> 3;
            int u = k4 * 128 + (row ^ k4);
            uint4 va = make_uint4(f2tf32(ra[p].x), f2tf32(ra[p].y),
                                  f2tf32(ra[p].z), f2tf32(ra[p].w));
            uint4 vb = make_uint4(f2tf32(rb[p].x), f2tf32(rb[p].y),
                                  f2tf32(rb[p].z), f2tf32(rb[p].w));
            *(uint4*)(bA + u * 4) = va;
            *(uint4*)(bB + u * 4) = vb;
        }
    };

    g_load(0);
    s_store(0);

    for (int c = 0; c < nCh; c++) {
        __syncthreads();
        if (c + 1 < nCh) g_load(c + 1);

        const uint32_t* bA = sm + (c & 1) * 8192;
        const uint32_t* bB = bA + 4096;

        #pragma unroll
        for (int ks = 0; ks < 4; ks++) {
            int k4a = 2 * ks, k4b = 2 * ks + 1;
            uint32_t afr[4][4];
            #pragma unroll
            for (int mt = 0; mt < 4; mt++) {
                int r = wm * 64 + mt * 16 + g;
                afr[mt][0] = bA[(k4a * 128 + (r ^ k4a)) * 4 + tig];
                afr[mt][1] = bA[(k4a * 128 + ((r + 8) ^ k4a)) * 4 + tig];
                afr[mt][2] = bA[(k4b * 128 + (r ^ k4b)) * 4 + tig];
                afr[mt][3] = bA[(k4b * 128 + ((r + 8) ^ k4b)) * 4 + tig];
            }
            uint32_t bfr[4][2];
            #pragma unroll
            for (int nt = 0; nt < 4; nt++) {
                int cn = wn * 32 + nt * 8 + g;
                bfr[nt][0] = bB[(k4a * 128 + (cn ^ k4a)) * 4 + tig];
                bfr[nt][1] = bB[(k4b * 128 + (cn ^ k4b)) * 4 + tig];
            }
            #pragma unroll
            for (int mt = 0; mt < 4; mt++)
                #pragma unroll
                for (int nt = 0; nt < 4; nt++)
                    mma_tf32(acc[mt][nt][0], acc[mt][nt][1],
                             acc[mt][nt][2], acc[mt][nt][3],
                             afr[mt][0], afr[mt][1], afr[mt][2], afr[mt][3],
                             bfr[nt][0], bfr[nt][1]);
        }

        if (c + 1 < nCh) s_store((c + 1) & 1);
    }

    // ---------------- Epilogue (via smem, fully coalesced stores) ----------------
    __syncthreads();
    float* ep = (float*)sm;                      // 128 x 132
    if (mode & 4) {
        // store transposed: ep[col][row]
        #pragma unroll
        for (int mt = 0; mt < 4; mt++) {
            int r = wm * 64 + mt * 16 + g;
            #pragma unroll
            for (int nt = 0; nt < 4; nt++) {
                int cn = wn * 32 + nt * 8 + 2 * tig;
                ep[cn * 132 + r]           = alpha * acc[mt][nt][0];
                ep[(cn + 1) * 132 + r]     = alpha * acc[mt][nt][1];
                ep[cn * 132 + r + 8]       = alpha * acc[mt][nt][2];
                ep[(cn + 1) * 132 + r + 8] = alpha * acc[mt][nt][3];
            }
        }
        __syncthreads();
        int b  = (by * BM) >> 10;
        int s0 = (by * BM) & 1023;
        #pragma unroll
        for (int p = 0; p < 16; p++) {
            int i4 = tid + p * 256;               // 4096 float4s
            int dd = i4 >> 5, s4 = i4 & 31;
            float4 v = *(const float4*)(ep + dd * 132 + s4 * 4);
            *(float4*)(C + ((long)(b * NHEAD + bx) * HDIM + dd) * SEQ + s0 + s4 * 4) = v;
        }
    } else {
        #pragma unroll
        for (int mt = 0; mt < 4; mt++) {
            int r = wm * 64 + mt * 16 + g;
            #pragma unroll
            for (int nt = 0; nt < 4; nt++) {
                int cn = wn * 32 + nt * 8 + 2 * tig;
                ep[r * 132 + cn]           = alpha * acc[mt][nt][0];
                ep[r * 132 + cn + 1]       = alpha * acc[mt][nt][1];
                ep[(r + 8) * 132 + cn]     = alpha * acc[mt][nt][2];
                ep[(r + 8) * 132 + cn + 1] = alpha * acc[mt][nt][3];
            }
        }
        __syncthreads();
        #pragma unroll
        for (int p = 0; p < 16; p++) {
            int i4 = tid + p * 256;
            int r = i4 >> 5, c4 = i4 & 31;
            float4 v = *(const float4*)(ep + r * 132 + c4 * 4);
            *(float4*)(C + ((long)by * BM + r) * ldc + bx * BN + c4 * 4) = v;
        }
    }
}

// ---------------- RoPE on [B,S,H,D] (in-place, rotate-half) ----------------
__global__ void rope_kernel(float* __restrict__ x,
                            const float* __restrict__ cosT,
                            const float* __restrict__ sinT)
{
    long i = (long)blockIdx.x * blockDim.x + threadIdx.x;
    long total = (long)MROWS * NHEAD * (HDIM / 2);
    if (i >= total) return;
    int d = (int)(i % (HDIM / 2));
    long rest = i / (HDIM / 2);          // (b*SEQ + s)*NHEAD + h
    int s = (int)((rest / NHEAD) % SEQ);
    float* base = x + rest * HDIM;
    float x1 = base[d], x2 = base[d + HDIM / 2];
    float c1 = cosT[s * HDIM + d],            s1 = sinT[s * HDIM + d];
    float c2 = cosT[s * HDIM + d + HDIM / 2], s2 = sinT[s * HDIM + d + HDIM / 2];
    base[d]            = x1 * c1 - x2 * s1;
    base[d + HDIM / 2] = x2 * c2 + x1 * s2;
}

// ---------------- Causal softmax over rows of g_s ----------------
__global__ void __launch_bounds__(256) softmax_kernel()
{
    long row = blockIdx.x;
    int q = (int)(row % SEQ);
    float* p = g_s + row * (long)SEQ;
    __shared__ float red[256];
    int tid = threadIdx.x;

    float m = -1e30f;
    for (int i = tid; i <= q; i += 256) m = fmaxf(m, p[i]);
    red[tid] = m; __syncthreads();
    for (int s = 128; s > 0; s >>= 1) {
        if (tid < s) red[tid] = fmaxf(red[tid], red[tid + s]);
        __syncthreads();
    }
    float mx = red[0]; __syncthreads();

    float sum = 0.f;
    for (int i = tid; i <= q; i += 256) {
        float e = __expf(p[i] - mx);
        p[i] = e;
        sum += e;
    }
    red[tid] = sum; __syncthreads();
    for (int s = 128; s > 0; s >>= 1) {
        if (tid < s) red[tid] += red[tid + s];
        __syncthreads();
    }
    float inv = 1.f / red[0];

    for (int i = tid; i <= q; i += 256) p[i] *= inv;
    for (int i = q + 1 + tid; i < SEQ; i += 256) p[i] = 0.f;
}

extern "C" void kernel_launch(void* const* d_in, const int* in_sizes, int n_in,
                              void* d_out, int out_size)
{
    const float* inQ  = (const float*)d_in[0];
    const float* inK  = (const float*)d_in[1];
    const float* inV  = (const float*)d_in[2];
    // d_in[3] = mask (causal, hard-coded)
    const float* cosT = (const float*)d_in[4];
    const float* sinT = (const float*)d_in[5];
    const float* Wq   = (const float*)d_in[6];
    const float* Wk   = (const float*)d_in[7];
    const float* Wv   = (const float*)d_in[8];
    const float* Wo   = (const float*)d_in[9];
    float* out = (float*)d_out;

    cudaFuncSetAttribute(gemm_tc, cudaFuncAttributeMaxDynamicSharedMemorySize, SMEM_BYTES);

    float *gq, *gk, *gv, *gs, *gctx;
    cudaGetSymbolAddress((void**)&gq,   g_q);
    cudaGetSymbolAddress((void**)&gk,   g_k);
    cudaGetSymbolAddress((void**)&gv,   g_v);
    cudaGetSymbolAddress((void**)&gs,   g_s);
    cudaGetSymbolAddress((void**)&gctx, g_ctx);

    const long SS = (long)SEQ * SEQ;
    const long SE = (long)SEQ * EMBED;
    const long DS = (long)HDIM * SEQ;

    dim3 pg(EMBED / BN, MROWS / BM, 1);   // 16 x 32

    // Projections. Q,K -> [B,S,E]; V -> [b,h,d,s] (mode 4).
    gemm_tc<<<pg, 256, SMEM_BYTES>>>(inQ, Wq, gq, EMBED, EMBED, EMBED,
                                     0, 0, 0, 0, 0, 0, 1, EMBED / BK, 1.0f, 0);
    gemm_tc<<<pg, 256, SMEM_BYTES>>>(inK, Wk, gk, EMBED, EMBED, EMBED,
                                     0, 0, 0, 0, 0, 0, 1, EMBED / BK, 1.0f, 0);
    gemm_tc<<<pg, 256, SMEM_BYTES>>>(inV, Wv, gv, EMBED, EMBED, 0,
                                     0, 0, 0, 0, 0, 0, 1, EMBED / BK, 1.0f, 4);

    // RoPE on Q and K (layout [B,S,H,D])
    long ropeN = (long)MROWS * NHEAD * (HDIM / 2);
    int ropeBlocks = (int)((ropeN + 255) / 256);
    rope_kernel<<<ropeBlocks, 256>>>(gq, cosT, sinT);
    rope_kernel<<<ropeBlocks, 256>>>(gk, cosT, sinT);

    // scores = Q @ K^T / sqrt(D); heads via pointer strides; causal block-skip
    float scale = 1.0f / sqrtf((float)HDIM);
    dim3 sg(SEQ / BN, SEQ / BM, BH);      // 8 x 8 x 64
    gemm_tc<<<sg, 256, SMEM_BYTES>>>(gq, gk, gs, EMBED, EMBED, SEQ,
                                     SE, (long)HDIM,
                                     SE, (long)HDIM,
                                     (long)NHEAD * SS, SS,
                                     NHEAD, HDIM / BK, scale, 1);

    softmax_kernel<<<BH * SEQ, 256>>>();

    // context = P @ V^T (V stored [b,h,d,s]); k-truncated at diagonal
    dim3 ag(HDIM / BN, SEQ / BM, BH);     // 1 x 8 x 64
    gemm_tc<<<ag, 256, SMEM_BYTES>>>(gs, gv, gctx, SEQ, SEQ, EMBED,
                                     (long)NHEAD * SS, SS,
                                     (long)NHEAD * DS, DS,
                                     SE, (long)HDIM,
                                     NHEAD, SEQ / BK, 1.0f, 2);

    // out = ctx @ Wo^T
    gemm_tc<<<pg, 256, SMEM_BYTES>>>(gctx, Wo, out, EMBED, EMBED, EMBED,
                                     0, 0, 0, 0, 0, 0, 1, EMBED / BK, 1.0f, 0);
}

// round 10
// speedup vs baseline: 3.3059x; 1.3110x over previous
#include <cuda_runtime.h>
#include <cstdint>
#include <math.h>

#define BATCH 4
#define SEQ   1024
#define EMBED 2048
#define NHEAD 16
#define HDIM  128
#define MROWS (BATCH*SEQ)     // 4096
#define BH    (BATCH*NHEAD)   // 64

#define BM 128
#define BN 128
#define BK 32

// Dynamic smem: max( double-buffer 2*(16KB+16KB)=64KB, epilogue 128*132*4=67584 )
#define SMEM_BYTES 67584

// Scratch
__device__ float g_q[(size_t)MROWS*EMBED];     // [B,S,E] = [b,s,h,d]
__device__ float g_k[(size_t)MROWS*EMBED];     // [B,S,E]
__device__ float g_v[(size_t)BH*HDIM*SEQ];     // [b,h,d,s]  (transposed V)
__device__ float g_s[(size_t)BH*SEQ*SEQ];      // scores / unnormalized probs
__device__ float g_ctx[(size_t)MROWS*EMBED];   // [B,S,E]
__device__ float g_linv[(size_t)BH*SEQ];       // per-row 1/sum(exp)

__device__ __forceinline__ uint32_t f2tf32(float f) {
    uint32_t u;
    asm("cvt.rna.tf32.f32 %0, %1;" : "=r"(u) : "f"(f));
    return u;
}

__device__ __forceinline__ void mma_tf32(float& d0, float& d1, float& d2, float& d3,
                                         uint32_t a0, uint32_t a1, uint32_t a2, uint32_t a3,
                                         uint32_t b0, uint32_t b1) {
    asm volatile(
        "mma.sync.aligned.m16n8k8.row.col.f32.tf32.tf32.f32 "
        "{%0,%1,%2,%3}, {%4,%5,%6,%7}, {%8,%9}, {%0,%1,%2,%3};"
        : "+f"(d0), "+f"(d1), "+f"(d2), "+f"(d3)
        : "r"(a0), "r"(a1), "r"(a2), "r"(a3), "r"(b0), "r"(b1));
}

__device__ __forceinline__ void ldsm_x4(uint32_t& r0, uint32_t& r1,
                                        uint32_t& r2, uint32_t& r3, uint32_t addr) {
    asm volatile("ldmatrix.sync.aligned.m8n8.x4.shared.b16 {%0,%1,%2,%3}, [%4];"
                 : "=r"(r0), "=r"(r1), "=r"(r2), "=r"(r3) : "r"(addr));
}

// ---------------- Generic tf32 mma.sync GEMM: C = alpha * A @ B^T ----------------
// A[M,K] lda, B[N,K] ldb (both K-contiguous).  z-batched via (z1,z2) strides.
// mode bit0: causal block-skip (bx>by)
// mode bit1: k-truncate at diagonal (AV)
// mode bit2: V-permute epilogue ([m=(b,s), n=(h=bx,d)] -> [b,h,d,s]); else row-major C.
// mode bit3: multiply output rows by rowScale[bz*SEQ + by*BM + r]
__global__ void __launch_bounds__(256, 2) gemm_tc(
    const float* __restrict__ A, const float* __restrict__ B, float* __restrict__ C,
    const float* __restrict__ rowScale,
    int lda, int ldb, int ldc,
    long sA1, long sA2, long sB1, long sB2, long sC1, long sC2,
    int zdiv, int nChunks, float alpha, int mode)
{
    int bx = blockIdx.x, by = blockIdx.y, bz = blockIdx.z;
    if ((mode & 1) && bx > by) return;
    int z1 = bz / zdiv, z2 = bz % zdiv;
    A += z1 * sA1 + z2 * sA2;
    B += z1 * sB1 + z2 * sB2;
    C += z1 * sC1 + z2 * sC2;
    const float* Ab = A + (long)by * BM * lda;
    const float* Bb = B + (long)bx * BN * ldb;

    extern __shared__ __align__(16) uint32_t sm[];
    uint32_t smBase = (uint32_t)__cvta_generic_to_shared(sm);

    int tid  = threadIdx.x;
    int lane = tid & 31, warp = tid >> 5;
    int g = lane >> 2, tig = lane & 3;
    int wm = warp & 1, wn = warp >> 1;          // 2 x 4 warp grid (64x32 tiles)
    int l7 = lane & 7, lb3 = (lane >> 3) & 1, lb4 = lane >> 4;

    float acc[4][4][4];
    #pragma unroll
    for (int mt = 0; mt < 4; mt++)
        #pragma unroll
        for (int nt = 0; nt < 4; nt++)
            #pragma unroll
            for (int e = 0; e < 4; e++) acc[mt][nt][e] = 0.f;

    int nCh = nChunks;
    if (mode & 2) nCh = min(nCh, (by + 1) * (BM / BK));

    float4 ra[4], rb[4];

    // global -> regs (coalesced: k fast within warp)
    auto g_load = [&](int c) {
        #pragma unroll
        for (int p = 0; p < 4; p++) {
            int f = tid + p * 256;
            int k4 = f & 7, row = f >> 3;
            ra[p] = *(const float4*)(Ab + (long)row * lda + c * BK + k4 * 4);
            rb[p] = *(const float4*)(Bb + (long)row * ldb + c * BK + k4 * 4);
        }
    };
    // regs -> smem (tf32 convert, swizzled cells: u = k4*128 + (row^k4))
    auto s_store = [&](int stage) {
        uint32_t* bA = sm + stage * 8192;
        uint32_t* bB = bA + 4096;
        #pragma unroll
        for (int p = 0; p < 4; p++) {
            int f = tid + p * 256;
            int k4 = f & 7, row = f >> 3;
            int u = k4 * 128 + (row ^ k4);
            uint4 va = make_uint4(f2tf32(ra[p].x), f2tf32(ra[p].y),
                                  f2tf32(ra[p].z), f2tf32(ra[p].w));
            uint4 vb = make_uint4(f2tf32(rb[p].x), f2tf32(rb[p].y),
                                  f2tf32(rb[p].z), f2tf32(rb[p].w));
            *(uint4*)(bA + u * 4) = va;
            *(uint4*)(bB + u * 4) = vb;
        }
    };

    g_load(0);
    s_store(0);

    for (int c = 0; c < nCh; c++) {
        __syncthreads();
        if (c + 1 < nCh) g_load(c + 1);

        uint32_t aSh = smBase + (c & 1) * 32768;
        uint32_t bSh = aSh + 16384;

        #pragma unroll
        for (int ks = 0; ks < 4; ks++) {
            int kqA = 2 * ks + lb4;             // A lanes: bit4 selects k-quarter
            int kqB = 2 * ks + lb3;             // B lanes: bit3 selects k-quarter
            uint32_t afr[4][4];
            #pragma unroll
            for (int mt = 0; mt < 4; mt++) {
                int r = wm * 64 + mt * 16 + l7 + 8 * lb3;
                uint32_t cell = kqA * 128 + (r ^ kqA);
                ldsm_x4(afr[mt][0], afr[mt][1], afr[mt][2], afr[mt][3],
                        aSh + cell * 16);
            }
            uint32_t bfr[4][2];
            #pragma unroll
            for (int pr = 0; pr < 2; pr++) {
                int rn = wn * 32 + pr * 16 + l7 + 8 * lb4;
                uint32_t cell = kqB * 128 + (rn ^ kqB);
                ldsm_x4(bfr[2 * pr][0], bfr[2 * pr][1],
                        bfr[2 * pr + 1][0], bfr[2 * pr + 1][1],
                        bSh + cell * 16);
            }
            #pragma unroll
            for (int mt = 0; mt < 4; mt++)
                #pragma unroll
                for (int nt = 0; nt < 4; nt++)
                    mma_tf32(acc[mt][nt][0], acc[mt][nt][1],
                             acc[mt][nt][2], acc[mt][nt][3],
                             afr[mt][0], afr[mt][1], afr[mt][2], afr[mt][3],
                             bfr[nt][0], bfr[nt][1]);
        }

        if (c + 1 < nCh) s_store((c + 1) & 1);
    }

    // Optional per-row scale (deferred softmax normalization)
    float rs[4][2];
    if (mode & 8) {
        const float* RS = rowScale + (long)bz * SEQ + by * BM;
        #pragma unroll
        for (int mt = 0; mt < 4; mt++) {
            int r = wm * 64 + mt * 16 + g;
            rs[mt][0] = RS[r];
            rs[mt][1] = RS[r + 8];
        }
    } else {
        #pragma unroll
        for (int mt = 0; mt < 4; mt++) { rs[mt][0] = 1.f; rs[mt][1] = 1.f; }
    }

    // ---------------- Epilogue (via smem, fully coalesced stores) ----------------
    __syncthreads();
    float* ep = (float*)sm;                      // 128 x 132
    if (mode & 4) {
        // store transposed: ep[col][row]
        #pragma unroll
        for (int mt = 0; mt < 4; mt++) {
            int r = wm * 64 + mt * 16 + g;
            #pragma unroll
            for (int nt = 0; nt < 4; nt++) {
                int cn = wn * 32 + nt * 8 + 2 * tig;
                ep[cn * 132 + r]           = alpha * acc[mt][nt][0];
                ep[(cn + 1) * 132 + r]     = alpha * acc[mt][nt][1];
                ep[cn * 132 + r + 8]       = alpha * acc[mt][nt][2];
                ep[(cn + 1) * 132 + r + 8] = alpha * acc[mt][nt][3];
            }
        }
        __syncthreads();
        int b  = (by * BM) >> 10;
        int s0 = (by * BM) & 1023;
        #pragma unroll
        for (int p = 0; p < 16; p++) {
            int i4 = tid + p * 256;               // 4096 float4s
            int dd = i4 >> 5, s4 = i4 & 31;
            float4 v = *(const float4*)(ep + dd * 132 + s4 * 4);
            *(float4*)(C + ((long)(b * NHEAD + bx) * HDIM + dd) * SEQ + s0 + s4 * 4) = v;
        }
    } else {
        #pragma unroll
        for (int mt = 0; mt < 4; mt++) {
            int r = wm * 64 + mt * 16 + g;
            #pragma unroll
            for (int nt = 0; nt < 4; nt++) {
                int cn = wn * 32 + nt * 8 + 2 * tig;
                ep[r * 132 + cn]           = alpha * rs[mt][0] * acc[mt][nt][0];
                ep[r * 132 + cn + 1]       = alpha * rs[mt][0] * acc[mt][nt][1];
                ep[(r + 8) * 132 + cn]     = alpha * rs[mt][1] * acc[mt][nt][2];
                ep[(r + 8) * 132 + cn + 1] = alpha * rs[mt][1] * acc[mt][nt][3];
            }
        }
        __syncthreads();
        #pragma unroll
        for (int p = 0; p < 16; p++) {
            int i4 = tid + p * 256;
            int r = i4 >> 5, c4 = i4 & 31;
            float4 v = *(const float4*)(ep + r * 132 + c4 * 4);
            *(float4*)(C + ((long)by * BM + r) * ldc + bx * BN + c4 * 4) = v;
        }
    }
}

// ---------------- RoPE on [B,S,H,D] (in-place, rotate-half) ----------------
__global__ void rope_kernel(float* __restrict__ x,
                            const float* __restrict__ cosT,
                            const float* __restrict__ sinT)
{
    long i = (long)blockIdx.x * blockDim.x + threadIdx.x;
    long total = (long)MROWS * NHEAD * (HDIM / 2);
    if (i >= total) return;
    int d = (int)(i % (HDIM / 2));
    long rest = i / (HDIM / 2);          // (b*SEQ + s)*NHEAD + h
    int s = (int)((rest / NHEAD) % SEQ);
    float* base = x + rest * HDIM;
    float x1 = base[d], x2 = base[d + HDIM / 2];
    float c1 = cosT[s * HDIM + d],            s1 = sinT[s * HDIM + d];
    float c2 = cosT[s * HDIM + d + HDIM / 2], s2 = sinT[s * HDIM + d + HDIM / 2];
    base[d]            = x1 * c1 - x2 * s1;
    base[d + HDIM / 2] = x2 * c2 + x1 * s2;
}

// ---------------- Causal softmax (2-pass, unnormalized; 1/sum -> g_linv) ----------
__global__ void __launch_bounds__(256) softmax_kernel()
{
    long row = blockIdx.x;
    int q = (int)(row % SEQ);
    float* p = g_s + row * (long)SEQ;
    float4* p4 = (float4*)p;
    __shared__ float red[256];
    int tid = threadIdx.x;
    int n = q + 1, n4 = n >> 2, tail0 = n4 << 2;

    // pass 1: max
    float m = -1e30f;
    for (int i = tid; i < n4; i += 256) {
        float4 v = p4[i];
        m = fmaxf(m, fmaxf(fmaxf(v.x, v.y), fmaxf(v.z, v.w)));
    }
    for (int i = tail0 + tid; i < n; i += 256) m = fmaxf(m, p[i]);
    red[tid] = m; __syncthreads();
    for (int s = 128; s > 0; s >>= 1) {
        if (tid < s) red[tid] = fmaxf(red[tid], red[tid + s]);
        __syncthreads();
    }
    float mx = red[0]; __syncthreads();

    // pass 2: exp (store unnormalized) + sum
    float sum = 0.f;
    for (int i = tid; i < n4; i += 256) {
        float4 v = p4[i];
        v.x = __expf(v.x - mx); v.y = __expf(v.y - mx);
        v.z = __expf(v.z - mx); v.w = __expf(v.w - mx);
        p4[i] = v;
        sum += (v.x + v.y) + (v.z + v.w);
    }
    for (int i = tail0 + tid; i < n; i += 256) {
        float e = __expf(p[i] - mx);
        p[i] = e;
        sum += e;
    }
    red[tid] = sum; __syncthreads();
    for (int s = 128; s > 0; s >>= 1) {
        if (tid < s) red[tid] += red[tid + s];
        __syncthreads();
    }
    if (tid == 0) g_linv[row] = 1.f / red[0];

    // zero-fill only to the 128-block boundary (AV reads no further)
    int kEnd = ((q >> 7) + 1) << 7;
    for (int i = n + tid; i < kEnd; i += 256) p[i] = 0.f;
}

extern "C" void kernel_launch(void* const* d_in, const int* in_sizes, int n_in,
                              void* d_out, int out_size)
{
    const float* inQ  = (const float*)d_in[0];
    const float* inK  = (const float*)d_in[1];
    const float* inV  = (const float*)d_in[2];
    // d_in[3] = mask (causal, hard-coded)
    const float* cosT = (const float*)d_in[4];
    const float* sinT = (const float*)d_in[5];
    const float* Wq   = (const float*)d_in[6];
    const float* Wk   = (const float*)d_in[7];
    const float* Wv   = (const float*)d_in[8];
    const float* Wo   = (const float*)d_in[9];
    float* out = (float*)d_out;

    cudaFuncSetAttribute(gemm_tc, cudaFuncAttributeMaxDynamicSharedMemorySize, SMEM_BYTES);

    float *gq, *gk, *gv, *gs, *gctx, *glinv;
    cudaGetSymbolAddress((void**)&gq,    g_q);
    cudaGetSymbolAddress((void**)&gk,    g_k);
    cudaGetSymbolAddress((void**)&gv,    g_v);
    cudaGetSymbolAddress((void**)&gs,    g_s);
    cudaGetSymbolAddress((void**)&gctx,  g_ctx);
    cudaGetSymbolAddress((void**)&glinv, g_linv);

    const long SS = (long)SEQ * SEQ;
    const long SE = (long)SEQ * EMBED;
    const long DS = (long)HDIM * SEQ;

    dim3 pg(EMBED / BN, MROWS / BM, 1);   // 16 x 32

    // Projections. Q,K -> [B,S,E]; V -> [b,h,d,s] (mode 4).
    gemm_tc<<<pg, 256, SMEM_BYTES>>>(inQ, Wq, gq, nullptr, EMBED, EMBED, EMBED,
                                     0, 0, 0, 0, 0, 0, 1, EMBED / BK, 1.0f, 0);
    gemm_tc<<<pg, 256, SMEM_BYTES>>>(inK, Wk, gk, nullptr, EMBED, EMBED, EMBED,
                                     0, 0, 0, 0, 0, 0, 1, EMBED / BK, 1.0f, 0);
    gemm_tc<<<pg, 256, SMEM_BYTES>>>(inV, Wv, gv, nullptr, EMBED, EMBED, 0,
                                     0, 0, 0, 0, 0, 0, 1, EMBED / BK, 1.0f, 4);

    // RoPE on Q and K (layout [B,S,H,D])
    long ropeN = (long)MROWS * NHEAD * (HDIM / 2);
    int ropeBlocks = (int)((ropeN + 255) / 256);
    rope_kernel<<<ropeBlocks, 256>>>(gq, cosT, sinT);
    rope_kernel<<<ropeBlocks, 256>>>(gk, cosT, sinT);

    // scores = Q @ K^T / sqrt(D); heads via pointer strides; causal block-skip
    float scale = 1.0f / sqrtf((float)HDIM);
    dim3 sg(SEQ / BN, SEQ / BM, BH);      // 8 x 8 x 64
    gemm_tc<<<sg, 256, SMEM_BYTES>>>(gq, gk, gs, nullptr, EMBED, EMBED, SEQ,
                                     SE, (long)HDIM,
                                     SE, (long)HDIM,
                                     (long)NHEAD * SS, SS,
                                     NHEAD, HDIM / BK, scale, 1);

    softmax_kernel<<<BH * SEQ, 256>>>();

    // context = P @ V^T (V stored [b,h,d,s]); k-truncated; row-normalized in epilogue
    dim3 ag(HDIM / BN, SEQ / BM, BH);     // 1 x 8 x 64
    gemm_tc<<<ag, 256, SMEM_BYTES>>>(gs, gv, gctx, glinv, SEQ, SEQ, EMBED,
                                     (long)NHEAD * SS, SS,
                                     (long)NHEAD * DS, DS,
                                     SE, (long)HDIM,
                                     NHEAD, SEQ / BK, 1.0f, 2 | 8);

    // out = ctx @ Wo^T
    gemm_tc<<<pg, 256, SMEM_BYTES>>>(gctx, Wo, out, nullptr, EMBED, EMBED, EMBED,
                                     0, 0, 0, 0, 0, 0, 1, EMBED / BK, 1.0f, 0);
}